// round 6
// baseline (speedup 1.0000x reference)
#include <cuda_runtime.h>

#define NN   80          // row length N
#define G    4           // threads per row
#define C    20          // recursion steps per thread (G*C == NN)
#define TPB  256
#define RPC  (TPB / G)   // rows per CTA = 64
#define RSO  164         // out-staging row stride in floats (41 float4) -> conflict-free

// One transfer-matrix step: new_top = (a - i)*x - b*y ; new_bottom = x.
__device__ __forceinline__ void mstep(float a, float b,
                                      float& xr, float& xi, float& yr, float& yi)
{
    float nr = a * xr + xi - b * yr;
    float ni = a * xi - xr - b * yi;
    yr = xr; yi = xi;
    xr = nr; xi = ni;
}

// 2x2 complex matmul C = A*B. Layout: {00r,00i,01r,01i,10r,10i,11r,11i}
__device__ __forceinline__ void mmul(const float* A, const float* B, float* Cm)
{
    Cm[0] = A[0]*B[0] - A[1]*B[1] + A[2]*B[4] - A[3]*B[5];
    Cm[1] = A[0]*B[1] + A[1]*B[0] + A[2]*B[5] + A[3]*B[4];
    Cm[2] = A[0]*B[2] - A[1]*B[3] + A[2]*B[6] - A[3]*B[7];
    Cm[3] = A[0]*B[3] + A[1]*B[2] + A[2]*B[7] + A[3]*B[6];
    Cm[4] = A[4]*B[0] - A[5]*B[1] + A[6]*B[4] - A[7]*B[5];
    Cm[5] = A[4]*B[1] + A[5]*B[0] + A[6]*B[5] + A[7]*B[4];
    Cm[6] = A[4]*B[2] - A[5]*B[3] + A[6]*B[6] - A[7]*B[7];
    Cm[7] = A[4]*B[3] + A[5]*B[2] + A[6]*B[7] + A[7]*B[6];
}

__global__ __launch_bounds__(TPB, 2)
void bk_green_scan4s_kernel(const float* __restrict__ he,
                            const float* __restrict__ h0d,
                            const float* __restrict__ h0s,
                            const float* __restrict__ h0p,
                            float* __restrict__ out,
                            int Brows)
{
    // dynamic smem: sIn[RPC*80] then sOut[RPC*RSO]
    extern __shared__ float sm[];
    float* sIn  = sm;                 // a values, row stride 80 floats
    float* sOut = sm + RPC * NN;      // g staging, row stride RSO floats
    __shared__ float bthS[NN];        // theta beta: bc[k-1], bthS[0]=0
    __shared__ float bcS[NN];         // bc[m], bcS[NN-1]=0 (phi beta via reversed idx)

    const int tid = threadIdx.x;
    const int l   = tid & (G - 1);
    const int lr  = tid >> 2;                 // local row
    const int rowBase = blockIdx.x * RPC;
    const int rows = min(RPC, Brows - rowBase);
    const unsigned mask = 0xffffffffu;

    if (tid < NN) {
        bcS[tid]  = (tid <= NN - 2) ? h0s[tid] * h0p[tid] : 0.0f;
        bthS[tid] = (tid == 0) ? 0.0f : h0s[tid - 1] * h0p[tid - 1];
    }

    // ---- coalesced staging: sIn[row][j] = he[row][j] + h0_diag[j] (float4) ----
    {
        const float4* he4 = (const float4*)(he + (size_t)rowBase * NN);
        const float4* d4  = (const float4*)h0d;
        float4* sIn4 = (float4*)sIn;
        for (int i = tid; i < rows * (NN / 4); i += TPB) {
            int c = i % (NN / 4);
            float4 hv = __ldg(he4 + i);
            float4 dv = __ldg(d4 + c);
            float4 v; v.x = hv.x + dv.x; v.y = hv.y + dv.y;
            v.z = hv.z + dv.z; v.w = hv.w + dv.w;
            sIn4[i] = v;
        }
    }
    __syncthreads();

    const int j0 = C * l;             // theta chunk start

    // ---- read own a-chunk from smem (LDS.128, conflict-free) ----
    float a_reg[C];
    {
        const float4* s4 = (const float4*)(sIn + lr * NN + j0);
        #pragma unroll
        for (int q = 0; q < C / 4; q++) {
            float4 v = s4[q];
            a_reg[4*q+0] = v.x; a_reg[4*q+1] = v.y;
            a_reg[4*q+2] = v.z; a_reg[4*q+3] = v.w;
        }
    }

    // ---- build chunk transfer products (theta + mirrored phi), 2 columns each ----
    float tur = 1.f, tui = 0.f, tvr = 0.f, tvi = 0.f;
    float tyr = 0.f, tyi = 0.f, twr = 1.f, twi = 0.f;
    float pur = 1.f, pui = 0.f, pvr = 0.f, pvi = 0.f;
    float pyr = 0.f, pyi = 0.f, pwr = 1.f, pwi = 0.f;
    #pragma unroll
    for (int r = 0; r < C; r++) {
        float at = a_reg[r],       bt = bthS[j0 + r];
        float ap = a_reg[C-1-r],   bp = bcS[j0 + C - 1 - r];
        mstep(at, bt, tur, tui, tyr, tyi);
        mstep(at, bt, tvr, tvi, twr, twi);
        mstep(ap, bp, pur, pui, pyr, pyi);
        mstep(ap, bp, pvr, pvi, pwr, pwi);
    }

    // ---- theta scan (ascending lanes, 2 rounds) ----
    float sxr, sxi, syr, syi, cdr, cdi;
    {
        float J[8] = { tur, tui, tvr, tvi, tyr, tyi, twr, twi };
        #pragma unroll
        for (int d = 1; d < G; d <<= 1) {
            float T[8], R[8];
            #pragma unroll
            for (int i = 0; i < 8; i++) T[i] = __shfl_up_sync(mask, J[i], d, G);
            mmul(J, T, R);
            bool use = (l >= d);
            #pragma unroll
            for (int i = 0; i < 8; i++) J[i] = use ? R[i] : J[i];
        }
        float dr = __shfl_sync(mask, J[0], G - 1, G);   // theta_N
        float di = __shfl_sync(mask, J[1], G - 1, G);
        float inv = 1.0f / (dr * dr + di * di);
        cdr = dr * inv; cdi = di * inv;
        float q0 = __shfl_up_sync(mask, J[0], 1, G);
        float q1 = __shfl_up_sync(mask, J[1], 1, G);
        float q4 = __shfl_up_sync(mask, J[4], 1, G);
        float q5 = __shfl_up_sync(mask, J[5], 1, G);
        sxr = (l == 0) ? 1.f : q0;
        sxi = (l == 0) ? 0.f : q1;
        syr = (l == 0) ? 0.f : q4;
        syi = (l == 0) ? 0.f : q5;
    }

    // ---- phi scan (descending lanes, 2 rounds) ----
    float pxr, pxi, qyr, qyi;
    {
        float J[8] = { pur, pui, pvr, pvi, pyr, pyi, pwr, pwi };
        #pragma unroll
        for (int d = 1; d < G; d <<= 1) {
            float T[8], R[8];
            #pragma unroll
            for (int i = 0; i < 8; i++) T[i] = __shfl_down_sync(mask, J[i], d, G);
            mmul(J, T, R);
            bool use = (l <= G - 1 - d);
            #pragma unroll
            for (int i = 0; i < 8; i++) J[i] = use ? R[i] : J[i];
        }
        float q0 = __shfl_down_sync(mask, J[0], 1, G);
        float q1 = __shfl_down_sync(mask, J[1], 1, G);
        float q4 = __shfl_down_sync(mask, J[4], 1, G);
        float q5 = __shfl_down_sync(mask, J[5], 1, G);
        pxr = (l == G - 1) ? 1.f : q0;
        pxi = (l == G - 1) ? 0.f : q1;
        qyr = (l == G - 1) ? 0.f : q4;
        qyi = (l == G - 1) ? 0.f : q5;
    }

    // ---- phi replay into registers ----
    float phr[C], phi_[C];
    #pragma unroll
    for (int r = 0; r < C; r++) {
        phr[r] = pxr; phi_[r] = pxi;          // phi_rev_{m0+r}
        float ap = a_reg[C-1-r], bp = bcS[j0 + C - 1 - r];
        mstep(ap, bp, pxr, pxi, qyr, qyi);
    }

    // ---- theta replay fused with num + g, staged to smem (STS.128) ----
    {
        float* so = sOut + lr * RSO + j0 * 2; // this thread's 40-float slice
        float gx = 0.f, gy = 0.f;
        #pragma unroll
        for (int r = 0; r < C; r++) {
            float qr = phr[C-1-r], qi = phi_[C-1-r];
            float nr = sxr * qr - sxi * qi;
            float ni = sxr * qi + sxi * qr;
            float g0 = nr * cdr + ni * cdi;
            float g1 = ni * cdr - nr * cdi;
            if ((r & 1) == 0) { gx = g0; gy = g1; }
            else {
                float4 g; g.x = gx; g.y = gy; g.z = g0; g.w = g1;
                *(float4*)(so + 2 * (r - 1)) = g;
            }
            float at = a_reg[r], bt = bthS[j0 + r];
            mstep(at, bt, sxr, sxi, syr, syi);
        }
    }
    __syncthreads();

    // ---- coalesced output: float4 copy smem -> global ----
    {
        float4* out4 = (float4*)out + (size_t)rowBase * (NN / 2);
        const float4* sOut4 = (const float4*)sOut;
        for (int i = tid; i < rows * (NN / 2); i += TPB) {
            int row = i / (NN / 2);
            int c   = i - row * (NN / 2);
            out4[i] = sOut4[row * (RSO / 4) + c];
        }
    }
}

extern "C" void kernel_launch(void* const* d_in, const int* in_sizes, int n_in,
                              void* d_out, int out_size)
{
    const float* he  = (const float*)d_in[0];   // he_diag (B*N)
    const float* h0d = (const float*)d_in[1];   // h0_diag (N)
    const float* h0s = (const float*)d_in[2];   // h0_sub  (N-1)
    const float* h0p = (const float*)d_in[3];   // h0_super(N-1)

    int Brows = in_sizes[0] / NN;
    size_t smem = (size_t)(RPC * NN + RPC * RSO) * sizeof(float);  // 62,464 B

    cudaFuncSetAttribute(bk_green_scan4s_kernel,
                         cudaFuncAttributeMaxDynamicSharedMemorySize, (int)smem);

    int grid = (Brows + RPC - 1) / RPC;
    bk_green_scan4s_kernel<<<grid, TPB, smem>>>(he, h0d, h0s, h0p, (float*)d_out, Brows);
}

// round 8
// speedup vs baseline: 1.1664x; 1.1664x over previous
#include <cuda_runtime.h>

#define NN  80          // row length N
#define G   4           // threads per row
#define C   20          // recursion steps per thread (G*C == NN)
#define TPB 256
#define RPC (TPB / G)   // rows per CTA = 64

// One transfer-matrix step: new_top = (a - i)*x - b*y ; new_bottom = x.
__device__ __forceinline__ void mstep(float a, float b,
                                      float& xr, float& xi, float& yr, float& yi)
{
    float nr = a * xr + xi - b * yr;
    float ni = a * xi - xr - b * yi;
    yr = xr; yi = xi;
    xr = nr; xi = ni;
}

// 2x2 complex matmul C = A*B. Layout: {00r,00i,01r,01i,10r,10i,11r,11i}
__device__ __forceinline__ void mmul(const float* A, const float* B, float* Cm)
{
    Cm[0] = A[0]*B[0] - A[1]*B[1] + A[2]*B[4] - A[3]*B[5];
    Cm[1] = A[0]*B[1] + A[1]*B[0] + A[2]*B[5] + A[3]*B[4];
    Cm[2] = A[0]*B[2] - A[1]*B[3] + A[2]*B[6] - A[3]*B[7];
    Cm[3] = A[0]*B[3] + A[1]*B[2] + A[2]*B[7] + A[3]*B[6];
    Cm[4] = A[4]*B[0] - A[5]*B[1] + A[6]*B[4] - A[7]*B[5];
    Cm[5] = A[4]*B[1] + A[5]*B[0] + A[6]*B[5] + A[7]*B[4];
    Cm[6] = A[4]*B[2] - A[5]*B[3] + A[6]*B[6] - A[7]*B[7];
    Cm[7] = A[4]*B[3] + A[5]*B[2] + A[6]*B[7] + A[7]*B[6];
}

__global__ __launch_bounds__(TPB, 3)
void bk_green_scan8_kernel(const float* __restrict__ he,
                           const float* __restrict__ h0d,
                           const float* __restrict__ h0s,
                           const float* __restrict__ h0p,
                           float* __restrict__ out,
                           int Brows)
{
    // bthS[k] = beta for theta step k (= bc[k-1], bthS[0]=0)
    // bcS[m]  = bc[m], bcS[NN-1] = 0 (phi replay beta via reversed index)
    __shared__ float bthS[NN];
    __shared__ float bcS[NN];

    const int tid = threadIdx.x;
    const int l   = tid & (G - 1);
    const int row = blockIdx.x * RPC + (tid >> 2);
    const unsigned mask = 0xffffffffu;

    if (tid < NN) {
        bcS[tid]  = (tid <= NN - 2) ? h0s[tid] * h0p[tid] : 0.0f;
        bthS[tid] = (tid == 0) ? 0.0f : h0s[tid - 1] * h0p[tid - 1];
    }
    __syncthreads();

    const int rowc = min(row, Brows - 1);
    const int j0 = C * l;

    // ---- load own a-chunk via float4 (80B-aligned rows) ----
    float a_reg[C];
    {
        const float4* h4 = (const float4*)(he + (size_t)rowc * NN + j0);
        const float4* d4 = (const float4*)(h0d + j0);
        #pragma unroll
        for (int q = 0; q < C / 4; q++) {
            float4 hv = __ldg(h4 + q);
            float4 dv = __ldg(d4 + q);
            a_reg[4*q + 0] = hv.x + dv.x;
            a_reg[4*q + 1] = hv.y + dv.y;
            a_reg[4*q + 2] = hv.z + dv.z;
            a_reg[4*q + 3] = hv.w + dv.w;
        }
    }

    // ---- build THETA chunk matrix only (2 columns) ----
    // layout {00r,00i,01r,01i,10r,10i,11r,11i}; col0 = (00,10), col1 = (01,11)
    float Jp[8] = {1.f,0.f, 0.f,0.f, 0.f,0.f, 1.f,0.f};
    #pragma unroll
    for (int r = 0; r < C; r++) {
        float at = a_reg[r], bt = bthS[j0 + r];
        mstep(at, bt, Jp[0], Jp[1], Jp[4], Jp[5]);   // col 0
        mstep(at, bt, Jp[2], Jp[3], Jp[6], Jp[7]);   // col 1
    }
    float Js[8];
    #pragma unroll
    for (int i = 0; i < 8; i++) Js[i] = Jp[i];

    // ---- ascending prefix scan (theta): Jp_l = T_l * T_{l-1} * ... * T_0 ----
    // ---- descending suffix scan:       Js_l = T_{G-1} * ... * T_l        ----
    #pragma unroll
    for (int d = 1; d < G; d <<= 1) {
        float Tu[8], Td[8], Ru[8], Rd[8];
        #pragma unroll
        for (int i = 0; i < 8; i++) Tu[i] = __shfl_up_sync(mask, Jp[i], d, G);
        #pragma unroll
        for (int i = 0; i < 8; i++) Td[i] = __shfl_down_sync(mask, Js[i], d, G);
        mmul(Jp, Tu, Ru);           // own * received (right-accumulate)
        mmul(Td, Js, Rd);           // received * own (left-accumulate)
        bool useu = (l >= d);
        bool used = (l <= G - 1 - d);
        #pragma unroll
        for (int i = 0; i < 8; i++) {
            Jp[i] = useu ? Ru[i] : Jp[i];
            Js[i] = used ? Rd[i] : Js[i];
        }
    }

    // denominator: theta_N = [Jp(lane G-1)]_00
    float cdr, cdi;
    {
        float dr = __shfl_sync(mask, Jp[0], G - 1, G);
        float di = __shfl_sync(mask, Jp[1], G - 1, G);
        float inv = 1.0f / (dr * dr + di * di);
        cdr = dr * inv; cdi = di * inv;
    }

    // theta exclusive prefix state: first column of lane l-1's Jp (lane 0: identity)
    float sxr, sxi, syr, syi;
    {
        float q0 = __shfl_up_sync(mask, Jp[0], 1, G);
        float q1 = __shfl_up_sync(mask, Jp[1], 1, G);
        float q4 = __shfl_up_sync(mask, Jp[4], 1, G);
        float q5 = __shfl_up_sync(mask, Jp[5], 1, G);
        sxr = (l == 0) ? 1.f : q0;
        sxi = (l == 0) ? 0.f : q1;
        syr = (l == 0) ? 0.f : q4;
        syi = (l == 0) ? 0.f : q5;
    }

    // phi boundary state from exclusive suffix T(p) = T_{G-1}***T_{l+1}, p = j0+C:
    //   T(p) = [[ K(p,n-1), -bc_{p-1} K(p+1,n-1) ], [ ... ]]
    //   phi top    = T[0][0]              (elements 0,1 of lane l+1's Js)
    //   phi bottom = -T[0][1] / bc_{p-1}  (elements 2,3, negated, scaled)
    float pxr, pxi, qyr, qyi;
    {
        float q0 = __shfl_down_sync(mask, Js[0], 1, G);
        float q1 = __shfl_down_sync(mask, Js[1], 1, G);
        float q2 = __shfl_down_sync(mask, Js[2], 1, G);
        float q3 = __shfl_down_sync(mask, Js[3], 1, G);
        float binv = 1.0f / bcS[j0 + C - 1];   // bc_{p-1}; garbage for l==G-1, selected away
        pxr = (l == G - 1) ? 1.f : q0;
        pxi = (l == G - 1) ? 0.f : q1;
        qyr = (l == G - 1) ? 0.f : (-q2 * binv);
        qyi = (l == G - 1) ? 0.f : (-q3 * binv);
    }

    // ---- phi replay into registers: phi_rev_{m0+r}, coef a[C-1-r], beta bcS[j0+C-1-r] ----
    float phr[C], phi_[C];
    #pragma unroll
    for (int r = 0; r < C; r++) {
        phr[r] = pxr; phi_[r] = pxi;
        float ap = a_reg[C-1-r], bp = bcS[j0 + C - 1 - r];
        mstep(ap, bp, pxr, pxi, qyr, qyi);
    }

    // ---- theta replay fused with num + output (direct float4 stores) ----
    if (row < Brows) {
        float4* out4 = (float4*)out;                 // out is (B, N, 2) floats
        size_t base = (size_t)row * (NN / 2) + (size_t)l * (C / 2);
        float gx = 0.f, gy = 0.f;
        #pragma unroll
        for (int r = 0; r < C; r++) {
            float qr = phr[C-1-r], qi = phi_[C-1-r];
            float nr = sxr * qr - sxi * qi;
            float ni = sxr * qi + sxi * qr;
            float g0 = nr * cdr + ni * cdi;
            float g1 = ni * cdr - nr * cdi;
            if ((r & 1) == 0) { gx = g0; gy = g1; }
            else {
                float4 g; g.x = gx; g.y = gy; g.z = g0; g.w = g1;
                out4[base + (r >> 1)] = g;
            }
            float at = a_reg[r], bt = bthS[j0 + r];
            mstep(at, bt, sxr, sxi, syr, syi);
        }
    }
}

extern "C" void kernel_launch(void* const* d_in, const int* in_sizes, int n_in,
                              void* d_out, int out_size)
{
    const float* he  = (const float*)d_in[0];   // he_diag (B*N)
    const float* h0d = (const float*)d_in[1];   // h0_diag (N)
    const float* h0s = (const float*)d_in[2];   // h0_sub  (N-1)
    const float* h0p = (const float*)d_in[3];   // h0_super(N-1)

    int Brows = in_sizes[0] / NN;
    int grid = (Brows + RPC - 1) / RPC;
    bk_green_scan8_kernel<<<grid, TPB>>>(he, h0d, h0s, h0p, (float*)d_out, Brows);
}

// round 9
// speedup vs baseline: 1.4710x; 1.2612x over previous
#include <cuda_runtime.h>

#define NN   80          // row length N
#define G    4           // threads per row
#define C    20          // recursion steps per thread (G*C == NN)
#define TPB  256
#define RPC  (TPB / G)   // rows per CTA = 64
#define RWPW 8           // rows per warp
#define WBUF 1312        // per-warp smem floats: 8 rows * 164 (41 float4) out view
#define SIN4 20          // in view: float4 per row (80 floats)
#define SOUT4 41         // out view: float4 row stride (164 floats)

// One transfer-matrix step: new_top = (a - i)*x - b*y ; new_bottom = x.
__device__ __forceinline__ void mstep(float a, float b,
                                      float& xr, float& xi, float& yr, float& yi)
{
    float nr = a * xr + xi - b * yr;
    float ni = a * xi - xr - b * yi;
    yr = xr; yi = xi;
    xr = nr; xi = ni;
}

// 2x2 complex matmul C = A*B. Layout: {00r,00i,01r,01i,10r,10i,11r,11i}
__device__ __forceinline__ void mmul(const float* A, const float* B, float* Cm)
{
    Cm[0] = A[0]*B[0] - A[1]*B[1] + A[2]*B[4] - A[3]*B[5];
    Cm[1] = A[0]*B[1] + A[1]*B[0] + A[2]*B[5] + A[3]*B[4];
    Cm[2] = A[0]*B[2] - A[1]*B[3] + A[2]*B[6] - A[3]*B[7];
    Cm[3] = A[0]*B[3] + A[1]*B[2] + A[2]*B[7] + A[3]*B[6];
    Cm[4] = A[4]*B[0] - A[5]*B[1] + A[6]*B[4] - A[7]*B[5];
    Cm[5] = A[4]*B[1] + A[5]*B[0] + A[6]*B[5] + A[7]*B[4];
    Cm[6] = A[4]*B[2] - A[5]*B[3] + A[6]*B[6] - A[7]*B[7];
    Cm[7] = A[4]*B[3] + A[5]*B[2] + A[6]*B[7] + A[7]*B[6];
}

__global__ __launch_bounds__(TPB, 3)
void bk_green_scan9_kernel(const float* __restrict__ he,
                           const float* __restrict__ h0d,
                           const float* __restrict__ h0s,
                           const float* __restrict__ h0p,
                           float* __restrict__ out,
                           int Brows)
{
    extern __shared__ float sm[];                 // 8 warps * WBUF floats
    __shared__ float bthS[NN];   // theta beta: bc[k-1], bthS[0]=0
    __shared__ float bcS[NN];    // bc[m], bcS[NN-1]=0

    const int tid  = threadIdx.x;
    const int lane = tid & 31;
    const int wid  = tid >> 5;
    const int l    = lane & (G - 1);
    const int lrow = lane >> 2;                   // local row within warp (0..7)
    const unsigned mask = 0xffffffffu;

    float* sW = sm + wid * WBUF;
    const int warpRow0 = blockIdx.x * RPC + wid * RWPW;
    const int row = warpRow0 + lrow;

    if (tid < NN) {
        bcS[tid]  = (tid <= NN - 2) ? h0s[tid] * h0p[tid] : 0.0f;
        bthS[tid] = (tid == 0) ? 0.0f : h0s[tid - 1] * h0p[tid - 1];
    }
    __syncthreads();

    // ---- warp-local coalesced in-staging: sW[row][j] = he + h0d ----
    {
        const float4* h4 = (const float4*)he;
        const float4* d4 = (const float4*)h0d;
        float4* sW4 = (float4*)sW;
        size_t gmax = (size_t)Brows * SIN4 - 1;
        size_t gbase = (size_t)warpRow0 * SIN4;
        #pragma unroll
        for (int k = 0; k < 5; k++) {
            int idx = lane + 32 * k;              // 0..159
            int c = idx % SIN4;
            size_t gidx = gbase + idx;
            if (gidx > gmax) gidx = gmax;
            float4 hv = __ldg(h4 + gidx);
            float4 dv = __ldg(d4 + c);
            float4 v; v.x = hv.x + dv.x; v.y = hv.y + dv.y;
            v.z = hv.z + dv.z; v.w = hv.w + dv.w;
            sW4[idx] = v;
        }
    }
    __syncwarp();

    const int j0 = C * l;

    // ---- read own a-chunk (LDS.128, stride 20 f4: conflict-free) ----
    float a_reg[C];
    {
        const float4* s4 = (const float4*)sW + lrow * SIN4 + l * 5;
        #pragma unroll
        for (int q = 0; q < C / 4; q++) {
            float4 v = s4[q];
            a_reg[4*q+0] = v.x; a_reg[4*q+1] = v.y;
            a_reg[4*q+2] = v.z; a_reg[4*q+3] = v.w;
        }
    }
    __syncwarp();   // in-buffer dead; out staging will reuse it

    // ---- build THETA chunk matrix only (2 columns) ----
    float Jp[8] = {1.f,0.f, 0.f,0.f, 0.f,0.f, 1.f,0.f};
    #pragma unroll
    for (int r = 0; r < C; r++) {
        float at = a_reg[r], bt = bthS[j0 + r];
        mstep(at, bt, Jp[0], Jp[1], Jp[4], Jp[5]);   // col 0
        mstep(at, bt, Jp[2], Jp[3], Jp[6], Jp[7]);   // col 1
    }
    float Js[8];
    #pragma unroll
    for (int i = 0; i < 8; i++) Js[i] = Jp[i];

    // ---- ascending prefix scan (theta) + descending suffix scan ----
    #pragma unroll
    for (int d = 1; d < G; d <<= 1) {
        float Tu[8], Td[8], Ru[8], Rd[8];
        #pragma unroll
        for (int i = 0; i < 8; i++) Tu[i] = __shfl_up_sync(mask, Jp[i], d, G);
        #pragma unroll
        for (int i = 0; i < 8; i++) Td[i] = __shfl_down_sync(mask, Js[i], d, G);
        mmul(Jp, Tu, Ru);           // own * received
        mmul(Td, Js, Rd);           // received * own
        bool useu = (l >= d);
        bool used = (l <= G - 1 - d);
        #pragma unroll
        for (int i = 0; i < 8; i++) {
            Jp[i] = useu ? Ru[i] : Jp[i];
            Js[i] = used ? Rd[i] : Js[i];
        }
    }

    // denominator: theta_N = [Jp(lane G-1)]_00
    float cdr, cdi;
    {
        float dr = __shfl_sync(mask, Jp[0], G - 1, G);
        float di = __shfl_sync(mask, Jp[1], G - 1, G);
        float inv = 1.0f / (dr * dr + di * di);
        cdr = dr * inv; cdi = di * inv;
    }

    // theta exclusive prefix state (lane 0: identity init (1,0))
    float sxr, sxi, syr, syi;
    {
        float q0 = __shfl_up_sync(mask, Jp[0], 1, G);
        float q1 = __shfl_up_sync(mask, Jp[1], 1, G);
        float q4 = __shfl_up_sync(mask, Jp[4], 1, G);
        float q5 = __shfl_up_sync(mask, Jp[5], 1, G);
        sxr = (l == 0) ? 1.f : q0;
        sxi = (l == 0) ? 0.f : q1;
        syr = (l == 0) ? 0.f : q4;
        syi = (l == 0) ? 0.f : q5;
    }

    // phi boundary from exclusive suffix T(p), p=j0+C:
    //   top = T[0][0]; bottom = -T[0][1] / bc_{p-1}
    float pxr, pxi, qyr, qyi;
    {
        float q0 = __shfl_down_sync(mask, Js[0], 1, G);
        float q1 = __shfl_down_sync(mask, Js[1], 1, G);
        float q2 = __shfl_down_sync(mask, Js[2], 1, G);
        float q3 = __shfl_down_sync(mask, Js[3], 1, G);
        float binv = 1.0f / bcS[j0 + C - 1];   // garbage for l==G-1, selected away
        pxr = (l == G - 1) ? 1.f : q0;
        pxi = (l == G - 1) ? 0.f : q1;
        qyr = (l == G - 1) ? 0.f : (-q2 * binv);
        qyi = (l == G - 1) ? 0.f : (-q3 * binv);
    }

    // ---- phi replay into registers ----
    float phr[C], phi_[C];
    #pragma unroll
    for (int r = 0; r < C; r++) {
        phr[r] = pxr; phi_[r] = pxi;
        float ap = a_reg[C-1-r], bp = bcS[j0 + C - 1 - r];
        mstep(ap, bp, pxr, pxi, qyr, qyi);
    }

    // ---- theta replay fused with num + g, staged to smem (stride 41 f4) ----
    {
        float4* so4 = (float4*)sW + lrow * SOUT4 + l * (C / 2);
        float gx = 0.f, gy = 0.f;
        #pragma unroll
        for (int r = 0; r < C; r++) {
            float qr = phr[C-1-r], qi = phi_[C-1-r];
            float nr = sxr * qr - sxi * qi;
            float ni = sxr * qi + sxi * qr;
            float g0 = nr * cdr + ni * cdi;
            float g1 = ni * cdr - nr * cdi;
            if ((r & 1) == 0) { gx = g0; gy = g1; }
            else {
                float4 g; g.x = gx; g.y = gy; g.z = g0; g.w = g1;
                so4[r >> 1] = g;
            }
            float at = a_reg[r], bt = bthS[j0 + r];
            mstep(at, bt, sxr, sxi, syr, syi);
        }
    }
    __syncwarp();

    // ---- coalesced out: smem (stride 41 f4) -> global float4 ----
    {
        const float4* so4 = (const float4*)sW;
        float4* out4 = (float4*)out + (size_t)warpRow0 * (NN / 2);
        #pragma unroll
        for (int k = 0; k < 10; k++) {
            int idx = lane + 32 * k;              // 0..319
            int r = idx / (NN / 2);
            int c = idx - r * (NN / 2);
            if (warpRow0 + r < Brows)
                out4[idx] = so4[r * SOUT4 + c];
        }
    }
}

extern "C" void kernel_launch(void* const* d_in, const int* in_sizes, int n_in,
                              void* d_out, int out_size)
{
    const float* he  = (const float*)d_in[0];   // he_diag (B*N)
    const float* h0d = (const float*)d_in[1];   // h0_diag (N)
    const float* h0s = (const float*)d_in[2];   // h0_sub  (N-1)
    const float* h0p = (const float*)d_in[3];   // h0_super(N-1)

    int Brows = in_sizes[0] / NN;
    size_t smem = (size_t)(TPB / 32) * WBUF * sizeof(float);   // 41,984 B

    cudaFuncSetAttribute(bk_green_scan9_kernel,
                         cudaFuncAttributeMaxDynamicSharedMemorySize, (int)smem);

    int grid = (Brows + RPC - 1) / RPC;
    bk_green_scan9_kernel<<<grid, TPB, smem>>>(he, h0d, h0s, h0p, (float*)d_out, Brows);
}

// round 10
// speedup vs baseline: 1.4791x; 1.0055x over previous
#include <cuda_runtime.h>

#define NN   80          // row length N
#define G    4           // threads per row
#define C    20          // recursion steps per thread (G*C == NN)
#define TPB  256
#define RPC  (TPB / G)   // rows per CTA = 64
#define RWPW 8           // rows per warp
#define WBUF 1312        // per-warp smem floats (out view: 8 rows * 164)
#define SIN4 20          // in view: float4 per row
#define SOUT4 41         // out view: float4 row stride

// One transfer-matrix step: new_top = (a - i)*x - b*y ; new_bottom = x.
__device__ __forceinline__ void mstep(float a, float b,
                                      float& xr, float& xi, float& yr, float& yi)
{
    float nr = a * xr + xi - b * yr;
    float ni = a * xi - xr - b * yi;
    yr = xr; yi = xi;
    xr = nr; xi = ni;
}

// 2x2 complex matmul C = A*B. Layout: {00r,00i,01r,01i,10r,10i,11r,11i}
__device__ __forceinline__ void mmul(const float* A, const float* B, float* Cm)
{
    Cm[0] = A[0]*B[0] - A[1]*B[1] + A[2]*B[4] - A[3]*B[5];
    Cm[1] = A[0]*B[1] + A[1]*B[0] + A[2]*B[5] + A[3]*B[4];
    Cm[2] = A[0]*B[2] - A[1]*B[3] + A[2]*B[6] - A[3]*B[7];
    Cm[3] = A[0]*B[3] + A[1]*B[2] + A[2]*B[7] + A[3]*B[6];
    Cm[4] = A[4]*B[0] - A[5]*B[1] + A[6]*B[4] - A[7]*B[5];
    Cm[5] = A[4]*B[1] + A[5]*B[0] + A[6]*B[5] + A[7]*B[4];
    Cm[6] = A[4]*B[2] - A[5]*B[3] + A[6]*B[6] - A[7]*B[7];
    Cm[7] = A[4]*B[3] + A[5]*B[2] + A[6]*B[7] + A[7]*B[6];
}

__global__ __launch_bounds__(TPB, 3)
void bk_green_scan10_kernel(const float* __restrict__ he,
                            const float* __restrict__ h0d,
                            const float* __restrict__ h0s,
                            const float* __restrict__ h0p,
                            float* __restrict__ out,
                            int Brows)
{
    extern __shared__ float sm[];                 // 8 warps * WBUF floats
    __shared__ float bthS[NN];   // theta beta: bc[k-1], bthS[0]=0
    __shared__ float bcS[NN];    // bc[m], bcS[NN-1]=0

    const int tid  = threadIdx.x;
    const int lane = tid & 31;
    const int wid  = tid >> 5;
    const int l    = lane & (G - 1);
    const int lrow = lane >> 2;                   // local row within warp
    const unsigned mask = 0xffffffffu;

    float* sW = sm + wid * WBUF;
    const int warpRow0 = blockIdx.x * RPC + wid * RWPW;

    if (tid < NN) {
        bcS[tid]  = (tid <= NN - 2) ? h0s[tid] * h0p[tid] : 0.0f;
        bthS[tid] = (tid == 0) ? 0.0f : h0s[tid - 1] * h0p[tid - 1];
    }
    __syncthreads();

    // ---- warp-local coalesced in-staging: sW[row][j] = he + h0d ----
    {
        const float4* h4 = (const float4*)he;
        const float4* d4 = (const float4*)h0d;
        float4* sW4 = (float4*)sW;
        size_t gmax = (size_t)Brows * SIN4 - 1;
        size_t gbase = (size_t)warpRow0 * SIN4;
        #pragma unroll
        for (int k = 0; k < 5; k++) {
            int idx = lane + 32 * k;              // 0..159
            int c = idx % SIN4;
            size_t gidx = gbase + idx;
            if (gidx > gmax) gidx = gmax;
            float4 hv = __ldg(h4 + gidx);
            float4 dv = __ldg(d4 + c);
            float4 v; v.x = hv.x + dv.x; v.y = hv.y + dv.y;
            v.z = hv.z + dv.z; v.w = hv.w + dv.w;
            sW4[idx] = v;
        }
    }
    __syncwarp();

    const int j0 = C * l;

    // ---- read own a-chunk (LDS.128, stride 20 f4: conflict-free) ----
    float a_reg[C];
    {
        const float4* s4 = (const float4*)sW + lrow * SIN4 + l * 5;
        #pragma unroll
        for (int q = 0; q < C / 4; q++) {
            float4 v = s4[q];
            a_reg[4*q+0] = v.x; a_reg[4*q+1] = v.y;
            a_reg[4*q+2] = v.z; a_reg[4*q+3] = v.w;
        }
    }
    __syncwarp();   // in-buffer dead; reused for out staging

    // ---- build THETA chunk matrix (2 columns) ----
    float Jp[8] = {1.f,0.f, 0.f,0.f, 0.f,0.f, 1.f,0.f};
    #pragma unroll
    for (int r = 0; r < C; r++) {
        float at = a_reg[r], bt = bthS[j0 + r];
        mstep(at, bt, Jp[0], Jp[1], Jp[4], Jp[5]);   // col 0
        mstep(at, bt, Jp[2], Jp[3], Jp[6], Jp[7]);   // col 1
    }
    float Js[8];
    #pragma unroll
    for (int i = 0; i < 8; i++) Js[i] = Jp[i];

    // ---- round d=1: full combines, both scans ----
    {
        float Tu[8], Td[8], Ru[8], Rd[8];
        #pragma unroll
        for (int i = 0; i < 8; i++) Tu[i] = __shfl_up_sync(mask, Jp[i], 1, G);
        #pragma unroll
        for (int i = 0; i < 8; i++) Td[i] = __shfl_down_sync(mask, Js[i], 1, G);
        mmul(Jp, Tu, Ru);           // own * received
        mmul(Td, Js, Rd);           // received * own
        bool useu = (l >= 1);
        bool used = (l <= G - 2);
        #pragma unroll
        for (int i = 0; i < 8; i++) {
            Jp[i] = useu ? Ru[i] : Jp[i];
            Js[i] = used ? Rd[i] : Js[i];
        }
    }

    // ---- round d=2 (final): partial combines ----
    {
        // ascending: only first column of result needed (prefix + denominator).
        float Tu0 = __shfl_up_sync(mask, Jp[0], 2, G);
        float Tu1 = __shfl_up_sync(mask, Jp[1], 2, G);
        float Tu4 = __shfl_up_sync(mask, Jp[4], 2, G);
        float Tu5 = __shfl_up_sync(mask, Jp[5], 2, G);
        float Ru0 = Jp[0]*Tu0 - Jp[1]*Tu1 + Jp[2]*Tu4 - Jp[3]*Tu5;
        float Ru1 = Jp[0]*Tu1 + Jp[1]*Tu0 + Jp[2]*Tu5 + Jp[3]*Tu4;
        float Ru4 = Jp[4]*Tu0 - Jp[5]*Tu1 + Jp[6]*Tu4 - Jp[7]*Tu5;
        float Ru5 = Jp[4]*Tu1 + Jp[5]*Tu0 + Jp[6]*Tu5 + Jp[7]*Tu4;
        bool useu = (l >= 2);
        Jp[0] = useu ? Ru0 : Jp[0];
        Jp[1] = useu ? Ru1 : Jp[1];
        Jp[4] = useu ? Ru4 : Jp[4];
        Jp[5] = useu ? Ru5 : Jp[5];

        // descending: only row 0 of result needed (phi boundary).
        float Td0 = __shfl_down_sync(mask, Js[0], 2, G);
        float Td1 = __shfl_down_sync(mask, Js[1], 2, G);
        float Td2 = __shfl_down_sync(mask, Js[2], 2, G);
        float Td3 = __shfl_down_sync(mask, Js[3], 2, G);
        float Rd0 = Td0*Js[0] - Td1*Js[1] + Td2*Js[4] - Td3*Js[5];
        float Rd1 = Td0*Js[1] + Td1*Js[0] + Td2*Js[5] + Td3*Js[4];
        float Rd2 = Td0*Js[2] - Td1*Js[3] + Td2*Js[6] - Td3*Js[7];
        float Rd3 = Td0*Js[3] + Td1*Js[2] + Td2*Js[7] + Td3*Js[6];
        bool used = (l <= G - 3);
        Js[0] = used ? Rd0 : Js[0];
        Js[1] = used ? Rd1 : Js[1];
        Js[2] = used ? Rd2 : Js[2];
        Js[3] = used ? Rd3 : Js[3];
    }

    // denominator: theta_N = [Jp(lane G-1)]_00 ; e = conj(theta_N)/|theta_N|^2
    float exr, exi;
    {
        float dr = __shfl_sync(mask, Jp[0], G - 1, G);
        float di = __shfl_sync(mask, Jp[1], G - 1, G);
        float inv = 1.0f / (dr * dr + di * di);
        exr = dr * inv; exi = -di * inv;
    }

    // theta exclusive prefix state, scaled by e (linearity: theta' = e*theta)
    float sxr, sxi, syr, syi;
    {
        float q0 = __shfl_up_sync(mask, Jp[0], 1, G);
        float q1 = __shfl_up_sync(mask, Jp[1], 1, G);
        float q4 = __shfl_up_sync(mask, Jp[4], 1, G);
        float q5 = __shfl_up_sync(mask, Jp[5], 1, G);
        float xr = (l == 0) ? 1.f : q0;
        float xi = (l == 0) ? 0.f : q1;
        float yr = (l == 0) ? 0.f : q4;
        float yi = (l == 0) ? 0.f : q5;
        sxr = xr * exr - xi * exi;  sxi = xr * exi + xi * exr;
        syr = yr * exr - yi * exi;  syi = yr * exi + yi * exr;
    }

    // phi boundary from exclusive suffix T(p), p=j0+C:
    //   top = T[0][0]; bottom = -T[0][1] / bc_{p-1}
    float pxr, pxi, qyr, qyi;
    {
        float q0 = __shfl_down_sync(mask, Js[0], 1, G);
        float q1 = __shfl_down_sync(mask, Js[1], 1, G);
        float q2 = __shfl_down_sync(mask, Js[2], 1, G);
        float q3 = __shfl_down_sync(mask, Js[3], 1, G);
        float nbinv = -1.0f / bcS[j0 + C - 1];   // garbage for l==G-1, selected away
        pxr = (l == G - 1) ? 1.f : q0;
        pxi = (l == G - 1) ? 0.f : q1;
        qyr = (l == G - 1) ? 0.f : (q2 * nbinv);
        qyi = (l == G - 1) ? 0.f : (q3 * nbinv);
    }

    // ---- phi replay into registers ----
    float phr[C], phi_[C];
    #pragma unroll
    for (int r = 0; r < C; r++) {
        phr[r] = pxr; phi_[r] = pxi;
        float ap = a_reg[C-1-r], bp = bcS[j0 + C - 1 - r];
        mstep(ap, bp, pxr, pxi, qyr, qyi);
    }

    // ---- theta' replay fused with g = theta' * phi, staged to smem ----
    {
        float4* so4 = (float4*)sW + lrow * SOUT4 + l * (C / 2);
        float gx = 0.f, gy = 0.f;
        #pragma unroll
        for (int r = 0; r < C; r++) {
            float qr = phr[C-1-r], qi = phi_[C-1-r];
            float g0 = sxr * qr - sxi * qi;
            float g1 = sxr * qi + sxi * qr;
            if ((r & 1) == 0) { gx = g0; gy = g1; }
            else {
                float4 g; g.x = gx; g.y = gy; g.z = g0; g.w = g1;
                so4[r >> 1] = g;
            }
            float at = a_reg[r], bt = bthS[j0 + r];
            mstep(at, bt, sxr, sxi, syr, syi);
        }
    }
    __syncwarp();

    // ---- coalesced out: smem (stride 41 f4) -> global float4 ----
    {
        const float4* so4 = (const float4*)sW;
        float4* out4 = (float4*)out + (size_t)warpRow0 * (NN / 2);
        #pragma unroll
        for (int k = 0; k < 10; k++) {
            int idx = lane + 32 * k;              // 0..319
            int r = idx / (NN / 2);
            int c = idx - r * (NN / 2);
            if (warpRow0 + r < Brows)
                out4[idx] = so4[r * SOUT4 + c];
        }
    }
}

extern "C" void kernel_launch(void* const* d_in, const int* in_sizes, int n_in,
                              void* d_out, int out_size)
{
    const float* he  = (const float*)d_in[0];   // he_diag (B*N)
    const float* h0d = (const float*)d_in[1];   // h0_diag (N)
    const float* h0s = (const float*)d_in[2];   // h0_sub  (N-1)
    const float* h0p = (const float*)d_in[3];   // h0_super(N-1)

    int Brows = in_sizes[0] / NN;
    size_t smem = (size_t)(TPB / 32) * WBUF * sizeof(float);   // 41,984 B

    cudaFuncSetAttribute(bk_green_scan10_kernel,
                         cudaFuncAttributeMaxDynamicSharedMemorySize, (int)smem);

    int grid = (Brows + RPC - 1) / RPC;
    bk_green_scan10_kernel<<<grid, TPB, smem>>>(he, h0d, h0s, h0p, (float*)d_out, Brows);
}